// round 1
// baseline (speedup 1.0000x reference)
#include <cuda_runtime.h>
#include <math.h>

// Problem constants
#define SEQ 50
#define DIM 32
#define NH  4
#define HDIM 8
#define NTHR 256
#define NWARP 8

__global__ __launch_bounds__(NTHR) void mha_fused_kernel(
    const float* __restrict__ Q, const float* __restrict__ K, const float* __restrict__ V,
    const float* __restrict__ ln_g, const float* __restrict__ ln_b,
    const float* __restrict__ Wq, const float* __restrict__ bq,
    const float* __restrict__ Wk, const float* __restrict__ bk,
    const float* __restrict__ Wv, const float* __restrict__ bv,
    const float* __restrict__ Wo, const float* __restrict__ bo,
    float* __restrict__ out)
{
    __shared__ __align__(16) float sQraw[SEQ * DIM];   // raw Q for residual
    __shared__ __align__(16) float sln[SEQ * DIM];     // LN buffer, reused as ctx
    __shared__ __align__(16) float sq[SEQ * DIM];
    __shared__ __align__(16) float sk[SEQ * DIM];
    __shared__ __align__(16) float sv[SEQ * DIM];
    __shared__ __align__(16) float sW[DIM * 33];       // padded weight tile
    __shared__ __align__(16) float sg[DIM], sb[DIM], sbias[DIM];

    const int b    = blockIdx.x;
    const int tid  = threadIdx.x;
    const int lane = tid & 31;
    const int wid  = tid >> 5;

    const size_t boff = (size_t)b * (SEQ * DIM);
    const float* Qb = Q + boff;
    const float* Kb = K + boff;
    const float* Vb = V + boff;

    // ---- helpers as lambdas ----
    auto load_tile4 = [&](float* dst, const float* src) {
        const float4* s4 = (const float4*)src;
        float4* d4 = (float4*)dst;
        #pragma unroll
        for (int i = tid; i < SEQ * DIM / 4; i += NTHR) d4[i] = s4[i];
    };
    auto load_weight = [&](const float* Wsrc, const float* bsrc) {
        for (int i = tid; i < DIM * DIM; i += NTHR) {
            int j = i >> 5, d = i & 31;
            sW[j * 33 + d] = Wsrc[i];
        }
        if (tid < DIM) sbias[tid] = bsrc[tid];
    };
    // LayerNorm rows of buf in place (warp per row)
    auto ln_rows = [&](float* buf) {
        for (int s = wid; s < SEQ; s += NWARP) {
            float x = buf[s * DIM + lane];
            float sum = x;
            #pragma unroll
            for (int o = 16; o; o >>= 1) sum += __shfl_xor_sync(0xffffffffu, sum, o);
            float mu = sum * (1.0f / DIM);
            float dx = x - mu;
            float vs = dx * dx;
            #pragma unroll
            for (int o = 16; o; o >>= 1) vs += __shfl_xor_sync(0xffffffffu, vs, o);
            float inv = rsqrtf(vs * (1.0f / DIM) + 1e-5f);
            buf[s * DIM + lane] = dx * inv * sg[lane] + sb[lane];
        }
    };
    // dst[s][j] = sbias[j] + sum_d src[s][d] * sW[j][d]
    auto project = [&](const float* src, float* dst) {
        const int j = tid & 31;
        for (int s = tid >> 5; s < SEQ; s += NWARP) {
            float acc = sbias[j];
            #pragma unroll
            for (int d = 0; d < DIM; d++)
                acc = fmaf(src[s * DIM + d], sW[j * 33 + d], acc);
            dst[s * DIM + j] = acc;
        }
    };

    // ---- Q: load raw (keep) + copy for LN; params; Wq ----
    {
        const float4* s4 = (const float4*)Qb;
        float4* dr = (float4*)sQraw;
        float4* dl = (float4*)sln;
        #pragma unroll
        for (int i = tid; i < SEQ * DIM / 4; i += NTHR) { float4 v = s4[i]; dr[i] = v; dl[i] = v; }
    }
    if (tid < DIM) { sg[tid] = ln_g[tid]; sb[tid] = ln_b[tid]; }
    load_weight(Wq, bq);
    __syncthreads();
    ln_rows(sln);
    __syncthreads();
    project(sln, sq);
    __syncthreads();

    // ---- K ----
    load_tile4(sln, Kb);
    load_weight(Wk, bk);
    __syncthreads();
    ln_rows(sln);
    __syncthreads();
    project(sln, sk);
    __syncthreads();

    // ---- V ----
    load_tile4(sln, Vb);
    load_weight(Wv, bv);
    __syncthreads();
    ln_rows(sln);
    __syncthreads();
    project(sln, sv);
    __syncthreads();

    // ---- Attention: thread per (head, query-row); ctx -> sln ----
    if (tid < NH * SEQ) {
        const int hh = tid / SEQ;
        const int ii = tid - hh * SEQ;
        const float* qrow = sq + ii * DIM + hh * HDIM;
        float4 qa = *(const float4*)qrow;
        float4 qc = *(const float4*)(qrow + 4);

        float sc[SEQ];
        float m = -1e30f;
        #pragma unroll
        for (int j = 0; j < SEQ; j++) {
            const float* kr = sk + j * DIM + hh * HDIM;
            float4 ka = *(const float4*)kr;
            float4 kc = *(const float4*)(kr + 4);
            float dot = qa.x * ka.x + qa.y * ka.y + qa.z * ka.z + qa.w * ka.w
                      + qc.x * kc.x + qc.y * kc.y + qc.z * kc.z + qc.w * kc.w;
            dot *= 0.35355339059327373f;   // 1/sqrt(8)
            sc[j] = dot;
            if (j <= ii) m = fmaxf(m, dot);
        }
        float ssum = 0.0f;
        #pragma unroll
        for (int j = 0; j < SEQ; j++) {
            float w = (j <= ii) ? __expf(sc[j] - m) : 0.0f;
            sc[j] = w;
            ssum += w;
        }
        float inv = 1.0f / ssum;
        float4 a0 = make_float4(0.f, 0.f, 0.f, 0.f);
        float4 a1 = make_float4(0.f, 0.f, 0.f, 0.f);
        #pragma unroll
        for (int j = 0; j < SEQ; j++) {
            float w = sc[j];
            const float* vr = sv + j * DIM + hh * HDIM;
            float4 va = *(const float4*)vr;
            float4 vc = *(const float4*)(vr + 4);
            a0.x += w * va.x; a0.y += w * va.y; a0.z += w * va.z; a0.w += w * va.w;
            a1.x += w * vc.x; a1.y += w * vc.y; a1.z += w * vc.z; a1.w += w * vc.w;
        }
        a0.x *= inv; a0.y *= inv; a0.z *= inv; a0.w *= inv;
        a1.x *= inv; a1.y *= inv; a1.z *= inv; a1.w *= inv;
        float* crow = sln + ii * DIM + hh * HDIM;
        *(float4*)crow = a0;
        *(float4*)(crow + 4) = a1;
    }
    // load Wo/bo (sW safe: last read finished before previous sync)
    load_weight(Wo, bo);
    __syncthreads();

    // ---- Output projection + residual ----
    {
        const int j = tid & 31;
        float* ob = out + boff;
        for (int s = tid >> 5; s < SEQ; s += NWARP) {
            float acc = sbias[j];
            #pragma unroll
            for (int d = 0; d < DIM; d++)
                acc = fmaf(sln[s * DIM + d], sW[j * 33 + d], acc);
            ob[s * DIM + j] = acc + sQraw[s * DIM + j];
        }
    }
}

extern "C" void kernel_launch(void* const* d_in, const int* in_sizes, int n_in,
                              void* d_out, int out_size) {
    const float* Q    = (const float*)d_in[0];
    const float* K    = (const float*)d_in[1];
    const float* V    = (const float*)d_in[2];
    // d_in[3] = mask (static causal triu, implemented analytically)
    const float* ln_g = (const float*)d_in[4];
    const float* ln_b = (const float*)d_in[5];
    const float* Wq   = (const float*)d_in[6];
    const float* bq   = (const float*)d_in[7];
    const float* Wk   = (const float*)d_in[8];
    const float* bk   = (const float*)d_in[9];
    const float* Wv   = (const float*)d_in[10];
    const float* bv   = (const float*)d_in[11];
    const float* Wo   = (const float*)d_in[12];
    const float* bo   = (const float*)d_in[13];
    float* out = (float*)d_out;

    const int B = in_sizes[0] / (SEQ * DIM);  // 16384
    mha_fused_kernel<<<B, NTHR>>>(Q, K, V, ln_g, ln_b,
                                  Wq, bq, Wk, bk, Wv, bv, Wo, bo, out);
}